// round 4
// baseline (speedup 1.0000x reference)
#include <cuda_runtime.h>
#include <math.h>

#define Bn   32
#define Cn   256
#define Hn   56
#define Wn   56
#define Gn   8
#define CGn  32
#define BGn  256
#define HWn  3136
#define EPSF 1e-5f

// ---------------- scratch (device globals; no allocation) ----------------
__device__ float g_xh[BGn*CGn*Hn];
__device__ float g_xw[BGn*CGn*Wn];
__device__ float g_corner[BGn*CGn*4];
__device__ float g_sigh[BGn*CGn*Hn];
__device__ float g_sigw[BGn*CGn*Wn];
__device__ float g_sum[BGn*CGn];
__device__ float g_sumsq[BGn*CGn];
__device__ float g_mu[BGn*CGn];
__device__ float g_isd[BGn*CGn];
__device__ float g_bm[Cn];
__device__ float g_ibsd[Cn];
__device__ float g_wa[CGn*9];           // sum_co x11[co]*w3a[co,ci,k]
__device__ float g_wb[Cn*9];            // mean_co w3b[co,ci,k]
__device__ float g_alpha[BGn*CGn];
__device__ float g_beta[BGn];
__device__ float g_scal[2];             // [0] = sum x11*b3a
__device__ float g_W1[BGn*HWn];
__device__ float g_part4[Gn*Bn*HWn];    // per-group partial of x4 channel-mean*Cn
__device__ float g_partP[Gn*Bn*HWn];    // per-group partial of x3 channel-sum
__device__ float g_x31[Bn*HWn];
__device__ float g_x41[Bn*HWn];
__device__ float g_T[Bn*Cn*9];
__device__ float g_B2[Bn*Cn];
__device__ float g_w2s[Bn*Cn];

__device__ __forceinline__ float sigmoidf(float v){ return 1.f/(1.f+expf(-v)); }

// ---------------- K1: per-plane row/col means + corners ----------------
__global__ void k1_plane(const float* __restrict__ x){
  __shared__ float sm[HWn];
  const int pc = blockIdx.x;
  const float* xp = x + (size_t)pc*HWn;
  for(int i=threadIdx.x;i<HWn/4;i+=blockDim.x)
    ((float4*)sm)[i]=((const float4*)xp)[i];
  __syncthreads();
  const int t=threadIdx.x;
  if(t<Hn){
    float s=0.f;
    #pragma unroll 8
    for(int j=0;j<Wn;j++) s+=sm[t*Wn+j];
    g_xh[pc*Hn+t]=s*(1.f/Wn);
  } else if(t>=64 && t<64+Wn){
    const int cx=t-64; float s=0.f;
    #pragma unroll 8
    for(int j=0;j<Hn;j++) s+=sm[j*Wn+cx];
    g_xw[pc*Wn+cx]=s*(1.f/Hn);
  } else if(t==126){
    g_corner[pc*4+0]=sm[0];
    g_corner[pc*4+1]=sm[55];
    g_corner[pc*4+2]=sm[55*56];
    g_corner[pc*4+3]=sm[55*56+55];
  }
}

// ---------------- K2: 1x1 conv over concat([x_h;x_w]) + sigmoid ----------------
__global__ void k2_conv1(const float* __restrict__ w1, const float* __restrict__ b1){
  const int bg=blockIdx.x;
  __shared__ float cat[CGn][112];
  __shared__ float ws[CGn*CGn];
  __shared__ float bs[CGn];
  for(int i=threadIdx.x;i<CGn*CGn;i+=blockDim.x) ws[i]=w1[i];
  if(threadIdx.x<CGn) bs[threadIdx.x]=b1[threadIdx.x];
  for(int i=threadIdx.x;i<CGn*112;i+=blockDim.x){
    const int ci=i/112, s=i%112;
    cat[ci][s] = (s<Hn) ? g_xh[(bg*CGn+ci)*Hn+s] : g_xw[(bg*CGn+ci)*Wn+(s-Hn)];
  }
  __syncthreads();
  for(int i=threadIdx.x;i<CGn*112;i+=blockDim.x){
    const int co=i/112, s=i%112;
    float a=bs[co];
    #pragma unroll
    for(int ci=0;ci<CGn;ci++) a=fmaf(ws[co*CGn+ci],cat[ci][s],a);
    const float sg=sigmoidf(a);
    if(s<Hn) g_sigh[(bg*CGn+co)*Hn+s]=sg;
    else     g_sigw[(bg*CGn+co)*Wn+(s-Hn)]=sg;
  }
}

// ---------------- K3: per-(bg,cg) stats of x0 (float4) ----------------
__global__ void k3_stats(const float* __restrict__ x){
  const int pc=blockIdx.x;
  __shared__ float sh[Hn], sw[Wn];
  __shared__ float r1[128], r2[128];
  const int t=threadIdx.x;
  if(t<Hn) sh[t]=g_sigh[pc*Hn+t];
  if(t>=64 && t<64+Wn) sw[t-64]=g_sigw[pc*Wn+(t-64)];
  __syncthreads();
  const float4* xp=(const float4*)(x+(size_t)pc*HWn);
  float s=0.f,s2=0.f;
  for(int i4=t;i4<HWn/4;i4+=128){
    const int y=i4/14, x0i=(i4-y*14)*4;
    const float4 f=xp[i4];
    const float shv=sh[y];
    float v;
    v=f.x*shv*sw[x0i+0]; s+=v; s2=fmaf(v,v,s2);
    v=f.y*shv*sw[x0i+1]; s+=v; s2=fmaf(v,v,s2);
    v=f.z*shv*sw[x0i+2]; s+=v; s2=fmaf(v,v,s2);
    v=f.w*shv*sw[x0i+3]; s+=v; s2=fmaf(v,v,s2);
  }
  r1[t]=s; r2[t]=s2; __syncthreads();
  for(int o=64;o;o>>=1){ if(t<o){ r1[t]+=r1[t+o]; r2[t]+=r2[t+o]; } __syncthreads(); }
  if(t==0){
    s=r1[0]; s2=r2[0];
    g_sum[pc]=s; g_sumsq[pc]=s2;
    const float mu=s*(1.f/HWn);
    const float var=s2*(1.f/HWn)-mu*mu;
    g_mu[pc]=mu;
    g_isd[pc]=rsqrtf(var+EPSF);
  }
}

// ---------------- K45: merged batch-stats / x11-wa / wb-mean ----------------
__global__ void k45(const float* __restrict__ gnb, const float* __restrict__ w3a,
                    const float* __restrict__ b3a, const float* __restrict__ w3b){
  const int blk=blockIdx.x, t=threadIdx.x;
  if(blk==0){
    if(t<Cn){
      const int c=t;
      float s=0.f,s2=0.f;
      for(int b=0;b<Bn;b++){ s+=g_sum[b*Cn+c]; s2+=g_sumsq[b*Cn+c]; }
      const float bm=s*(1.f/((float)Bn*HWn));
      const float bv=s2*(1.f/((float)Bn*HWn))-bm*bm;
      g_bm[c]=bm;
      g_ibsd[c]=rsqrtf(bv+EPSF);
    }
  } else if(blk==1){
    __shared__ float x11[CGn];
    if(t==0){
      float m=-1e30f;
      for(int i=0;i<CGn;i++) m=fmaxf(m,gnb[i]);
      float e[CGn]; float s=0.f;
      for(int i=0;i<CGn;i++){ e[i]=expf(gnb[i]-m); s+=e[i]; }
      float ba=0.f;
      for(int i=0;i<CGn;i++){ x11[i]=e[i]/s; ba=fmaf(x11[i],b3a[i],ba); }
      g_scal[0]=ba;
    }
    __syncthreads();
    for(int i=t;i<CGn*9;i+=blockDim.x){
      float a=0.f;
      for(int co=0;co<CGn;co++) a=fmaf(x11[co],w3a[co*CGn*9+i],a);
      g_wa[i]=a;
    }
  } else {
    const int k=blk-2;           // 0..8
    if(t<Cn){
      float a=0.f;
      for(int co=0;co<Cn;co++) a+=w3b[(size_t)co*Cn*9+t*9+k];
      g_wb[t*9+k]=a*(1.f/Cn);
    }
  }
}

// ---------------- K5c: x21 (exact conv means via window sums), alpha, beta ----------------
__global__ void k5c(const float* __restrict__ w3a, const float* __restrict__ b3a,
                    const float* __restrict__ gnw, const float* __restrict__ gnb){
  const int bg=blockIdx.x;
  const int co=threadIdx.x;   // 32 threads
  __shared__ float Ss[CGn][9];
  {
    const int ci=co;
    const int pc=bg*CGn+ci;
    float tot=0.f;
    for(int r=0;r<Hn;r++) tot+=g_xh[pc*Hn+r];
    tot*=(float)Wn;
    const float r0=g_xh[pc*Hn+0]*Wn,  r55=g_xh[pc*Hn+55]*Wn;
    const float c0=g_xw[pc*Wn+0]*Hn,  c55=g_xw[pc*Wn+55]*Hn;
    const float k00=g_corner[pc*4+0], k0w=g_corner[pc*4+1];
    const float kh0=g_corner[pc*4+2], khw=g_corner[pc*4+3];
    for(int dy=-1;dy<=1;dy++)for(int dx=-1;dx<=1;dx++){
      float s=tot;
      if(dy==-1)s-=r55;  if(dy==1)s-=r0;
      if(dx==-1)s-=c55;  if(dx==1)s-=c0;
      if(dy==-1&&dx==-1)s+=khw;
      if(dy==-1&&dx== 1)s+=kh0;
      if(dy== 1&&dx==-1)s+=k0w;
      if(dy== 1&&dx== 1)s+=k00;
      Ss[ci][(dy+1)*3+(dx+1)]=s;
    }
  }
  __syncthreads();
  float acc=0.f;
  for(int ci=0;ci<CGn;ci++){
    #pragma unroll
    for(int k=0;k<9;k++) acc=fmaf(w3a[(co*CGn+ci)*9+k],Ss[ci][k],acc);
  }
  float m2=b3a[co]+acc*(1.f/HWn);
  float mx=m2;
  for(int o=16;o;o>>=1) mx=fmaxf(mx,__shfl_xor_sync(0xffffffffu,mx,o));
  float e=expf(m2-mx), se=e;
  for(int o=16;o;o>>=1) se+=__shfl_xor_sync(0xffffffffu,se,o);
  const float x21=e/se;
  const int pc=bg*CGn+co;
  const float isd=g_isd[pc], mu=g_mu[pc];
  g_alpha[pc]=x21*gnw[co]*isd;
  float bt=x21*(gnb[co]-gnw[co]*mu*isd);
  for(int o=16;o;o>>=1) bt+=__shfl_xor_sync(0xffffffffu,bt,o);
  if(co==0) g_beta[bg]=bt+g_scal[0];
}

// ---------------- K6: fused big pass, split by group -> 1792 CTAs ----------------
__global__ void __launch_bounds__(448) k6_fused(const float* __restrict__ x){
  const int b=blockIdx.y, y0=blockIdx.x*8, g=blockIdx.z;
  const int t=threadIdx.x;
  __shared__ float tile[2][580];
  __shared__ float ssh[2][8], ssw[2][56];
  __shared__ float swa[288], swb[288], salpha[32], sibsd[32];
  __shared__ float sbeta;
  for(int i=t;i<288;i+=448){ swa[i]=g_wa[i]; swb[i]=g_wb[g*288+i]; }
  if(t<32){ salpha[t]=g_alpha[b*256+g*32+t]; sibsd[t]=g_ibsd[g*32+t]; }
  if(t==32) sbeta=g_beta[b*8+g];

  const int py=t/56, px=t%56;
  float accA=0.f,accB=0.f,acc4=0.f,accP=0.f;
  const int base=b*256+g*32;

  // prefetch c=0
  {
    const float* xp=x+(size_t)base*HWn;
    for(int i=t;i<580;i+=448){
      const int ty=i/58, tx=i%58, gy=y0-1+ty, gx2=tx-1;
      tile[0][i]=(gy>=0&&gy<Hn&&gx2>=0&&gx2<Wn)?xp[gy*Wn+gx2]:0.f;
    }
    if(t<8) ssh[0][t]=g_sigh[(size_t)base*Hn+y0+t];
    if(t>=64&&t<120) ssw[0][t-64]=g_sigw[(size_t)base*Wn+(t-64)];
  }
  __syncthreads();

  for(int c=0;c<32;c++){
    const int cur=c&1, nxt=cur^1;
    float p0=0.f,p1=0.f,psh=0.f,psw=0.f;
    if(c+1<32){
      const float* xp=x+(size_t)(base+c+1)*HWn;
      { const int ty=t/58, tx=t%58, gy=y0-1+ty, gx2=tx-1;
        p0=(gy>=0&&gy<Hn&&gx2>=0&&gx2<Wn)?xp[gy*Wn+gx2]:0.f; }
      if(t+448<580){ const int i1=t+448; const int ty=i1/58, tx=i1%58;
        const int gy=y0-1+ty, gx2=tx-1;
        p1=(gy>=0&&gy<Hn&&gx2>=0&&gx2<Wn)?xp[gy*Wn+gx2]:0.f; }
      if(t<8) psh=g_sigh[(size_t)(base+c+1)*Hn+y0+t];
      if(t>=64&&t<120) psw=g_sigw[(size_t)(base+c+1)*Wn+(t-64)];
    }
    const float* wap=&swa[c*9];
    const float* wbp=&swb[c*9];
    float ca=0.f,c4=0.f;
    #pragma unroll
    for(int ky=0;ky<3;ky++){
      #pragma unroll
      for(int kx=0;kx<3;kx++){
        const float v=tile[cur][(py+ky)*58+px+kx];
        ca=fmaf(wap[ky*3+kx],v,ca);
        c4=fmaf(wbp[ky*3+kx],v,c4);
      }
    }
    accA+=ca; acc4+=c4;
    const float v0=tile[cur][(py+1)*58+px+1]*ssh[cur][py]*ssw[cur][px];
    accB=fmaf(salpha[c],v0,accB);
    accP=fmaf(sibsd[c],v0,accP);
    __syncthreads();
    if(c+1<32){
      tile[nxt][t]=p0;
      if(t+448<580) tile[nxt][t+448]=p1;
      if(t<8) ssh[nxt][t]=psh;
      if(t>=64&&t<120) ssw[nxt][t-64]=psw;
    }
    __syncthreads();
  }
  const int p=(y0+py)*Wn+px;
  g_W1[(size_t)(b*8+g)*HWn+p]=accA+accB+sbeta;
  g_part4[(size_t)(g*Bn+b)*HWn+p]=acc4;
  g_partP[(size_t)(g*Bn+b)*HWn+p]=accP;
}

// ---------------- K7: reduce partials + softmax over 3136 pixels ----------------
__global__ void k7_softmax(){
  const int which=blockIdx.x, b=blockIdx.y;
  __shared__ float sv[HWn];
  __shared__ float red[256];
  const int t=threadIdx.x;
  const float* part = which ? g_part4 : g_partP;
  for(int i=t;i<HWn;i+=256){
    float s=0.f;
    #pragma unroll
    for(int g2=0;g2<Gn;g2++) s+=part[(size_t)(g2*Bn+b)*HWn+i];
    sv[i]= which ? s : s*(1.f/256.f);
  }
  __syncthreads();
  float m=-1e30f;
  for(int i=t;i<HWn;i+=256) m=fmaxf(m,sv[i]);
  red[t]=m; __syncthreads();
  for(int o=128;o;o>>=1){ if(t<o) red[t]=fmaxf(red[t],red[t+o]); __syncthreads(); }
  m=red[0]; __syncthreads();
  float s=0.f;
  for(int i=t;i<HWn;i+=256) s+=expf(sv[i]-m);
  red[t]=s; __syncthreads();
  for(int o=128;o;o>>=1){ if(t<o) red[t]+=red[t+o]; __syncthreads(); }
  const float inv=1.f/red[0];
  float* dst=(which? g_x41 : g_x31)+(size_t)b*HWn;
  for(int i=t;i<HWn;i+=256) dst[i]=expf(sv[i]-m)*inv;
}

// ---------------- K8: T (9-shift correlation) + B2, padded halo ----------------
__global__ void __launch_bounds__(256) k8_T(const float* __restrict__ x){
  const int pc=blockIdx.x;
  const int b=pc>>8;
  __shared__ float s31[58*58];
  __shared__ float s41[HWn];
  __shared__ float sh[Hn], sw[Wn];
  __shared__ float wred[8][10];
  const int t=threadIdx.x;
  for(int i=t;i<58*58;i+=256) s31[i]=0.f;
  __syncthreads();
  {
    const float* p31=g_x31+(size_t)b*HWn;
    const float* p41=g_x41+(size_t)b*HWn;
    for(int i=t;i<HWn;i+=256){
      const int y=i/56, xx=i-y*56;
      s31[(y+1)*58+xx+1]=p31[i];
      s41[i]=p41[i];
    }
  }
  if(t<Hn) sh[t]=g_sigh[pc*Hn+t];
  if(t>=64&&t<64+Wn) sw[t-64]=g_sigw[pc*Wn+(t-64)];
  __syncthreads();
  const float* xp=x+(size_t)pc*HWn;
  float acc[9]={0,0,0,0,0,0,0,0,0};
  float accB=0.f;
  for(int p=t;p<HWn;p+=256){
    const int y=p/56, xx=p-y*56;
    const float v=xp[p];
    const int ib=(y+1)*58+xx+1;
    // tap k=(dy+1)*3+(dx+1): s31[ib - dy*58 - dx]
    acc[0]=fmaf(v,s31[ib+58+1],acc[0]);
    acc[1]=fmaf(v,s31[ib+58  ],acc[1]);
    acc[2]=fmaf(v,s31[ib+58-1],acc[2]);
    acc[3]=fmaf(v,s31[ib   +1],acc[3]);
    acc[4]=fmaf(v,s31[ib     ],acc[4]);
    acc[5]=fmaf(v,s31[ib   -1],acc[5]);
    acc[6]=fmaf(v,s31[ib-58+1],acc[6]);
    acc[7]=fmaf(v,s31[ib-58  ],acc[7]);
    acc[8]=fmaf(v,s31[ib-58-1],acc[8]);
    accB=fmaf(v*sh[y]*sw[xx],s41[p],accB);
  }
  const int warp=t>>5, lane=t&31;
  #pragma unroll
  for(int k=0;k<9;k++){
    float a=acc[k];
    for(int o=16;o;o>>=1) a+=__shfl_xor_sync(0xffffffffu,a,o);
    if(lane==0) wred[warp][k]=a;
  }
  { float a=accB;
    for(int o=16;o;o>>=1) a+=__shfl_xor_sync(0xffffffffu,a,o);
    if(lane==0) wred[warp][9]=a; }
  __syncthreads();
  if(t<10){
    float a=0.f;
    #pragma unroll
    for(int w2=0;w2<8;w2++) a+=wred[w2][t];
    if(t<9) g_T[(size_t)pc*9+t]=a;
    else    g_B2[pc]=a;
  }
}

// ---------------- K9: A2 GEMV + weights2 -> sigmoid ----------------
__global__ void k9_A2(const float* __restrict__ w3b, const float* __restrict__ b3b){
  const int b=blockIdx.x;
  __shared__ float sT[2304];
  const int t=threadIdx.x;
  for(int i=t;i<2304;i+=256) sT[i]=g_T[(size_t)b*2304+i];
  __syncthreads();
  const int warp=t>>5, lane=t&31;
  for(int j=0;j<32;j++){
    const int c=warp*32+j;
    float a=0.f;
    for(int i=lane;i<2304;i+=32) a=fmaf(w3b[(size_t)c*2304+i],sT[i],a);
    for(int o=16;o;o>>=1) a+=__shfl_xor_sync(0xffffffffu,a,o);
    if(lane==0){
      const float w2=a+b3b[c]+g_ibsd[c]*(g_B2[b*Cn+c]-g_bm[c]);
      g_w2s[b*Cn+c]=sigmoidf(w2);
    }
  }
}

// ---------------- K10: final elementwise combine (float4) ----------------
__global__ void k10_final(const float* __restrict__ x, float* __restrict__ out){
  const int plane=blockIdx.x;
  const int bg=plane>>5;
  const float w2=g_w2s[plane];
  const float4* xp=(const float4*)(x+(size_t)plane*HWn);
  const float4* wp=(const float4*)(g_W1+(size_t)bg*HWn);
  float4* op=(float4*)(out+(size_t)plane*HWn);
  for(int i=threadIdx.x;i<HWn/4;i+=blockDim.x){
    const float4 xv=xp[i], wv=wp[i];
    float4 o;
    o.x=xv.x*(sigmoidf(wv.x)+w2);
    o.y=xv.y*(sigmoidf(wv.y)+w2);
    o.z=xv.z*(sigmoidf(wv.z)+w2);
    o.w=xv.w*(sigmoidf(wv.w)+w2);
    op[i]=o;
  }
}

// ---------------- launch ----------------
extern "C" void kernel_launch(void* const* d_in, const int* in_sizes, int n_in,
                              void* d_out, int out_size){
  const float* x  =(const float*)d_in[0];
  const float* w1 =(const float*)d_in[1];
  const float* b1 =(const float*)d_in[2];
  const float* w3a=(const float*)d_in[3];
  const float* b3a=(const float*)d_in[4];
  const float* w3b=(const float*)d_in[5];
  const float* b3b=(const float*)d_in[6];
  const float* gnw=(const float*)d_in[7];
  const float* gnb=(const float*)d_in[8];
  float* out=(float*)d_out;

  k1_plane<<<BGn*CGn,128>>>(x);
  k2_conv1<<<BGn,128>>>(w1,b1);
  k3_stats<<<BGn*CGn,128>>>(x);
  k45<<<11,288>>>(gnb,w3a,b3a,w3b);
  k5c<<<BGn,CGn>>>(w3a,b3a,gnw,gnb);
  k6_fused<<<dim3(7,Bn,Gn),448>>>(x);
  k7_softmax<<<dim3(2,Bn),256>>>();
  k8_T<<<Bn*Cn,256>>>(x);
  k9_A2<<<Bn,256>>>(w3b,b3b);
  k10_final<<<BGn*CGn,256>>>(x,out);
}

// round 5
// speedup vs baseline: 1.0006x; 1.0006x over previous
#include <cuda_runtime.h>
#include <math.h>

#define Bn   32
#define Cn   256
#define Hn   56
#define Wn   56
#define Gn   8
#define CGn  32
#define BGn  256
#define HWn  3136
#define EPSF 1e-5f

// ---------------- scratch (device globals; no allocation) ----------------
__device__ float g_xh[BGn*CGn*Hn];
__device__ float g_xw[BGn*CGn*Wn];
__device__ float g_corner[BGn*CGn*4];
__device__ float g_sigh[BGn*CGn*Hn];
__device__ float g_sigw[BGn*CGn*Wn];
__device__ float g_sum[BGn*CGn];
__device__ float g_sumsq[BGn*CGn];
__device__ float g_mu[BGn*CGn];
__device__ float g_isd[BGn*CGn];
__device__ float g_bm[Cn];
__device__ float g_ibsd[Cn];
__device__ float g_wa[CGn*9];           // sum_co x11[co]*w3a[co,ci,k]
__device__ float g_wb[Cn*9];            // mean_co w3b[co,ci,k]
__device__ float g_alpha[BGn*CGn];
__device__ float g_beta[BGn];
__device__ float g_scal[2];             // [0] = sum x11*b3a
__device__ float g_W1[BGn*HWn];
__device__ float g_part4[Gn*Bn*HWn];    // per-group partial of x4 channel-mean*Cn
__device__ float g_partP[Gn*Bn*HWn];    // per-group partial of x3 channel-sum
__device__ float g_x31[Bn*HWn];
__device__ float g_x41[Bn*HWn];
__device__ float g_T[Bn*Cn*9];
__device__ float g_B2[Bn*Cn];
__device__ float g_w2s[Bn*Cn];

__device__ __forceinline__ float sigmoidf(float v){ return 1.f/(1.f+expf(-v)); }

// ---------------- K1: per-plane row/col means + corners ----------------
__global__ void k1_plane(const float* __restrict__ x){
  __shared__ float sm[HWn];
  const int pc = blockIdx.x;
  const float* xp = x + (size_t)pc*HWn;
  for(int i=threadIdx.x;i<HWn/4;i+=blockDim.x)
    ((float4*)sm)[i]=((const float4*)xp)[i];
  __syncthreads();
  const int t=threadIdx.x;
  if(t<Hn){
    float s=0.f;
    #pragma unroll 8
    for(int j=0;j<Wn;j++) s+=sm[t*Wn+j];
    g_xh[pc*Hn+t]=s*(1.f/Wn);
  } else if(t>=64 && t<64+Wn){
    const int cx=t-64; float s=0.f;
    #pragma unroll 8
    for(int j=0;j<Hn;j++) s+=sm[j*Wn+cx];
    g_xw[pc*Wn+cx]=s*(1.f/Hn);
  } else if(t==126){
    g_corner[pc*4+0]=sm[0];
    g_corner[pc*4+1]=sm[55];
    g_corner[pc*4+2]=sm[55*56];
    g_corner[pc*4+3]=sm[55*56+55];
  }
}

// ---------------- K2: 1x1 conv over concat([x_h;x_w]) + sigmoid ----------------
__global__ void k2_conv1(const float* __restrict__ w1, const float* __restrict__ b1){
  const int bg=blockIdx.x;
  __shared__ float cat[CGn][112];
  __shared__ float ws[CGn*CGn];
  __shared__ float bs[CGn];
  for(int i=threadIdx.x;i<CGn*CGn;i+=blockDim.x) ws[i]=w1[i];
  if(threadIdx.x<CGn) bs[threadIdx.x]=b1[threadIdx.x];
  for(int i=threadIdx.x;i<CGn*112;i+=blockDim.x){
    const int ci=i/112, s=i%112;
    cat[ci][s] = (s<Hn) ? g_xh[(bg*CGn+ci)*Hn+s] : g_xw[(bg*CGn+ci)*Wn+(s-Hn)];
  }
  __syncthreads();
  for(int i=threadIdx.x;i<CGn*112;i+=blockDim.x){
    const int co=i/112, s=i%112;
    float a=bs[co];
    #pragma unroll
    for(int ci=0;ci<CGn;ci++) a=fmaf(ws[co*CGn+ci],cat[ci][s],a);
    const float sg=sigmoidf(a);
    if(s<Hn) g_sigh[(bg*CGn+co)*Hn+s]=sg;
    else     g_sigw[(bg*CGn+co)*Wn+(s-Hn)]=sg;
  }
}

// ---------------- K3: per-(bg,cg) stats of x0 (float4) ----------------
__global__ void k3_stats(const float* __restrict__ x){
  const int pc=blockIdx.x;
  __shared__ float sh[Hn], sw[Wn];
  __shared__ float r1[128], r2[128];
  const int t=threadIdx.x;
  if(t<Hn) sh[t]=g_sigh[pc*Hn+t];
  if(t>=64 && t<64+Wn) sw[t-64]=g_sigw[pc*Wn+(t-64)];
  __syncthreads();
  const float4* xp=(const float4*)(x+(size_t)pc*HWn);
  float s=0.f,s2=0.f;
  for(int i4=t;i4<HWn/4;i4+=128){
    const int y=i4/14, x0i=(i4-y*14)*4;
    const float4 f=xp[i4];
    const float shv=sh[y];
    float v;
    v=f.x*shv*sw[x0i+0]; s+=v; s2=fmaf(v,v,s2);
    v=f.y*shv*sw[x0i+1]; s+=v; s2=fmaf(v,v,s2);
    v=f.z*shv*sw[x0i+2]; s+=v; s2=fmaf(v,v,s2);
    v=f.w*shv*sw[x0i+3]; s+=v; s2=fmaf(v,v,s2);
  }
  r1[t]=s; r2[t]=s2; __syncthreads();
  for(int o=64;o;o>>=1){ if(t<o){ r1[t]+=r1[t+o]; r2[t]+=r2[t+o]; } __syncthreads(); }
  if(t==0){
    s=r1[0]; s2=r2[0];
    g_sum[pc]=s; g_sumsq[pc]=s2;
    const float mu=s*(1.f/HWn);
    const float var=s2*(1.f/HWn)-mu*mu;
    g_mu[pc]=mu;
    g_isd[pc]=rsqrtf(var+EPSF);
  }
}

// ---------------- K45: merged batch-stats / x11-wa / wb-mean ----------------
__global__ void k45(const float* __restrict__ gnb, const float* __restrict__ w3a,
                    const float* __restrict__ b3a, const float* __restrict__ w3b){
  const int blk=blockIdx.x, t=threadIdx.x;
  if(blk==0){
    if(t<Cn){
      const int c=t;
      float s=0.f,s2=0.f;
      for(int b=0;b<Bn;b++){ s+=g_sum[b*Cn+c]; s2+=g_sumsq[b*Cn+c]; }
      const float bm=s*(1.f/((float)Bn*HWn));
      const float bv=s2*(1.f/((float)Bn*HWn))-bm*bm;
      g_bm[c]=bm;
      g_ibsd[c]=rsqrtf(bv+EPSF);
    }
  } else if(blk==1){
    __shared__ float x11[CGn];
    if(t==0){
      float m=-1e30f;
      for(int i=0;i<CGn;i++) m=fmaxf(m,gnb[i]);
      float e[CGn]; float s=0.f;
      for(int i=0;i<CGn;i++){ e[i]=expf(gnb[i]-m); s+=e[i]; }
      float ba=0.f;
      for(int i=0;i<CGn;i++){ x11[i]=e[i]/s; ba=fmaf(x11[i],b3a[i],ba); }
      g_scal[0]=ba;
    }
    __syncthreads();
    for(int i=t;i<CGn*9;i+=blockDim.x){
      float a=0.f;
      for(int co=0;co<CGn;co++) a=fmaf(x11[co],w3a[co*CGn*9+i],a);
      g_wa[i]=a;
    }
  } else {
    const int k=blk-2;           // 0..8
    if(t<Cn){
      float a=0.f;
      for(int co=0;co<Cn;co++) a+=w3b[(size_t)co*Cn*9+t*9+k];
      g_wb[t*9+k]=a*(1.f/Cn);
    }
  }
}

// ---------------- K5c: x21 (exact conv means via window sums), alpha, beta ----------------
__global__ void k5c(const float* __restrict__ w3a, const float* __restrict__ b3a,
                    const float* __restrict__ gnw, const float* __restrict__ gnb){
  const int bg=blockIdx.x;
  const int co=threadIdx.x;   // 32 threads
  __shared__ float Ss[CGn][9];
  {
    const int ci=co;
    const int pc=bg*CGn+ci;
    float tot=0.f;
    for(int r=0;r<Hn;r++) tot+=g_xh[pc*Hn+r];
    tot*=(float)Wn;
    const float r0=g_xh[pc*Hn+0]*Wn,  r55=g_xh[pc*Hn+55]*Wn;
    const float c0=g_xw[pc*Wn+0]*Hn,  c55=g_xw[pc*Wn+55]*Hn;
    const float k00=g_corner[pc*4+0], k0w=g_corner[pc*4+1];
    const float kh0=g_corner[pc*4+2], khw=g_corner[pc*4+3];
    for(int dy=-1;dy<=1;dy++)for(int dx=-1;dx<=1;dx++){
      float s=tot;
      if(dy==-1)s-=r55;  if(dy==1)s-=r0;
      if(dx==-1)s-=c55;  if(dx==1)s-=c0;
      if(dy==-1&&dx==-1)s+=khw;
      if(dy==-1&&dx== 1)s+=kh0;
      if(dy== 1&&dx==-1)s+=k0w;
      if(dy== 1&&dx== 1)s+=k00;
      Ss[ci][(dy+1)*3+(dx+1)]=s;
    }
  }
  __syncthreads();
  float acc=0.f;
  for(int ci=0;ci<CGn;ci++){
    #pragma unroll
    for(int k=0;k<9;k++) acc=fmaf(w3a[(co*CGn+ci)*9+k],Ss[ci][k],acc);
  }
  float m2=b3a[co]+acc*(1.f/HWn);
  float mx=m2;
  for(int o=16;o;o>>=1) mx=fmaxf(mx,__shfl_xor_sync(0xffffffffu,mx,o));
  float e=expf(m2-mx), se=e;
  for(int o=16;o;o>>=1) se+=__shfl_xor_sync(0xffffffffu,se,o);
  const float x21=e/se;
  const int pc=bg*CGn+co;
  const float isd=g_isd[pc], mu=g_mu[pc];
  g_alpha[pc]=x21*gnw[co]*isd;
  float bt=x21*(gnb[co]-gnw[co]*mu*isd);
  for(int o=16;o;o>>=1) bt+=__shfl_xor_sync(0xffffffffu,bt,o);
  if(co==0) g_beta[bg]=bt+g_scal[0];
}

// ---------------- K6: fused big pass, split by group -> 1792 CTAs ----------------
__global__ void __launch_bounds__(448) k6_fused(const float* __restrict__ x){
  const int b=blockIdx.y, y0=blockIdx.x*8, g=blockIdx.z;
  const int t=threadIdx.x;
  __shared__ float tile[2][580];
  __shared__ float ssh[2][8], ssw[2][56];
  __shared__ float swa[288], swb[288], salpha[32], sibsd[32];
  __shared__ float sbeta;
  for(int i=t;i<288;i+=448){ swa[i]=g_wa[i]; swb[i]=g_wb[g*288+i]; }
  if(t<32){ salpha[t]=g_alpha[b*256+g*32+t]; sibsd[t]=g_ibsd[g*32+t]; }
  if(t==32) sbeta=g_beta[b*8+g];

  const int py=t/56, px=t%56;
  float accA=0.f,accB=0.f,acc4=0.f,accP=0.f;
  const int base=b*256+g*32;

  // prefetch c=0
  {
    const float* xp=x+(size_t)base*HWn;
    for(int i=t;i<580;i+=448){
      const int ty=i/58, tx=i%58, gy=y0-1+ty, gx2=tx-1;
      tile[0][i]=(gy>=0&&gy<Hn&&gx2>=0&&gx2<Wn)?xp[gy*Wn+gx2]:0.f;
    }
    if(t<8) ssh[0][t]=g_sigh[(size_t)base*Hn+y0+t];
    if(t>=64&&t<120) ssw[0][t-64]=g_sigw[(size_t)base*Wn+(t-64)];
  }
  __syncthreads();

  for(int c=0;c<32;c++){
    const int cur=c&1, nxt=cur^1;
    float p0=0.f,p1=0.f,psh=0.f,psw=0.f;
    if(c+1<32){
      const float* xp=x+(size_t)(base+c+1)*HWn;
      { const int ty=t/58, tx=t%58, gy=y0-1+ty, gx2=tx-1;
        p0=(gy>=0&&gy<Hn&&gx2>=0&&gx2<Wn)?xp[gy*Wn+gx2]:0.f; }
      if(t+448<580){ const int i1=t+448; const int ty=i1/58, tx=i1%58;
        const int gy=y0-1+ty, gx2=tx-1;
        p1=(gy>=0&&gy<Hn&&gx2>=0&&gx2<Wn)?xp[gy*Wn+gx2]:0.f; }
      if(t<8) psh=g_sigh[(size_t)(base+c+1)*Hn+y0+t];
      if(t>=64&&t<120) psw=g_sigw[(size_t)(base+c+1)*Wn+(t-64)];
    }
    const float* wap=&swa[c*9];
    const float* wbp=&swb[c*9];
    float ca=0.f,c4=0.f;
    #pragma unroll
    for(int ky=0;ky<3;ky++){
      #pragma unroll
      for(int kx=0;kx<3;kx++){
        const float v=tile[cur][(py+ky)*58+px+kx];
        ca=fmaf(wap[ky*3+kx],v,ca);
        c4=fmaf(wbp[ky*3+kx],v,c4);
      }
    }
    accA+=ca; acc4+=c4;
    const float v0=tile[cur][(py+1)*58+px+1]*ssh[cur][py]*ssw[cur][px];
    accB=fmaf(salpha[c],v0,accB);
    accP=fmaf(sibsd[c],v0,accP);
    __syncthreads();
    if(c+1<32){
      tile[nxt][t]=p0;
      if(t+448<580) tile[nxt][t+448]=p1;
      if(t<8) ssh[nxt][t]=psh;
      if(t>=64&&t<120) ssw[nxt][t-64]=psw;
    }
    __syncthreads();
  }
  const int p=(y0+py)*Wn+px;
  g_W1[(size_t)(b*8+g)*HWn+p]=accA+accB+sbeta;
  g_part4[(size_t)(g*Bn+b)*HWn+p]=acc4;
  g_partP[(size_t)(g*Bn+b)*HWn+p]=accP;
}

// ---------------- K7: reduce partials + softmax over 3136 pixels ----------------
__global__ void k7_softmax(){
  const int which=blockIdx.x, b=blockIdx.y;
  __shared__ float sv[HWn];
  __shared__ float red[256];
  const int t=threadIdx.x;
  const float* part = which ? g_part4 : g_partP;
  for(int i=t;i<HWn;i+=256){
    float s=0.f;
    #pragma unroll
    for(int g2=0;g2<Gn;g2++) s+=part[(size_t)(g2*Bn+b)*HWn+i];
    sv[i]= which ? s : s*(1.f/256.f);
  }
  __syncthreads();
  float m=-1e30f;
  for(int i=t;i<HWn;i+=256) m=fmaxf(m,sv[i]);
  red[t]=m; __syncthreads();
  for(int o=128;o;o>>=1){ if(t<o) red[t]=fmaxf(red[t],red[t+o]); __syncthreads(); }
  m=red[0]; __syncthreads();
  float s=0.f;
  for(int i=t;i<HWn;i+=256) s+=expf(sv[i]-m);
  red[t]=s; __syncthreads();
  for(int o=128;o;o>>=1){ if(t<o) red[t]+=red[t+o]; __syncthreads(); }
  const float inv=1.f/red[0];
  float* dst=(which? g_x41 : g_x31)+(size_t)b*HWn;
  for(int i=t;i<HWn;i+=256) dst[i]=expf(sv[i]-m)*inv;
}

// ---------------- K8: T (9-shift correlation) + B2, padded halo ----------------
__global__ void __launch_bounds__(256) k8_T(const float* __restrict__ x){
  const int pc=blockIdx.x;
  const int b=pc>>8;
  __shared__ float s31[58*58];
  __shared__ float s41[HWn];
  __shared__ float sh[Hn], sw[Wn];
  __shared__ float wred[8][10];
  const int t=threadIdx.x;
  for(int i=t;i<58*58;i+=256) s31[i]=0.f;
  __syncthreads();
  {
    const float* p31=g_x31+(size_t)b*HWn;
    const float* p41=g_x41+(size_t)b*HWn;
    for(int i=t;i<HWn;i+=256){
      const int y=i/56, xx=i-y*56;
      s31[(y+1)*58+xx+1]=p31[i];
      s41[i]=p41[i];
    }
  }
  if(t<Hn) sh[t]=g_sigh[pc*Hn+t];
  if(t>=64&&t<64+Wn) sw[t-64]=g_sigw[pc*Wn+(t-64)];
  __syncthreads();
  const float* xp=x+(size_t)pc*HWn;
  float acc[9]={0,0,0,0,0,0,0,0,0};
  float accB=0.f;
  for(int p=t;p<HWn;p+=256){
    const int y=p/56, xx=p-y*56;
    const float v=xp[p];
    const int ib=(y+1)*58+xx+1;
    // tap k=(dy+1)*3+(dx+1): s31[ib - dy*58 - dx]
    acc[0]=fmaf(v,s31[ib+58+1],acc[0]);
    acc[1]=fmaf(v,s31[ib+58  ],acc[1]);
    acc[2]=fmaf(v,s31[ib+58-1],acc[2]);
    acc[3]=fmaf(v,s31[ib   +1],acc[3]);
    acc[4]=fmaf(v,s31[ib     ],acc[4]);
    acc[5]=fmaf(v,s31[ib   -1],acc[5]);
    acc[6]=fmaf(v,s31[ib-58+1],acc[6]);
    acc[7]=fmaf(v,s31[ib-58  ],acc[7]);
    acc[8]=fmaf(v,s31[ib-58-1],acc[8]);
    accB=fmaf(v*sh[y]*sw[xx],s41[p],accB);
  }
  const int warp=t>>5, lane=t&31;
  #pragma unroll
  for(int k=0;k<9;k++){
    float a=acc[k];
    for(int o=16;o;o>>=1) a+=__shfl_xor_sync(0xffffffffu,a,o);
    if(lane==0) wred[warp][k]=a;
  }
  { float a=accB;
    for(int o=16;o;o>>=1) a+=__shfl_xor_sync(0xffffffffu,a,o);
    if(lane==0) wred[warp][9]=a; }
  __syncthreads();
  if(t<10){
    float a=0.f;
    #pragma unroll
    for(int w2=0;w2<8;w2++) a+=wred[w2][t];
    if(t<9) g_T[(size_t)pc*9+t]=a;
    else    g_B2[pc]=a;
  }
}

// ---------------- K9: A2 GEMV + weights2 -> sigmoid ----------------
__global__ void k9_A2(const float* __restrict__ w3b, const float* __restrict__ b3b){
  const int b=blockIdx.x;
  __shared__ float sT[2304];
  const int t=threadIdx.x;
  for(int i=t;i<2304;i+=256) sT[i]=g_T[(size_t)b*2304+i];
  __syncthreads();
  const int warp=t>>5, lane=t&31;
  for(int j=0;j<32;j++){
    const int c=warp*32+j;
    float a=0.f;
    for(int i=lane;i<2304;i+=32) a=fmaf(w3b[(size_t)c*2304+i],sT[i],a);
    for(int o=16;o;o>>=1) a+=__shfl_xor_sync(0xffffffffu,a,o);
    if(lane==0){
      const float w2=a+b3b[c]+g_ibsd[c]*(g_B2[b*Cn+c]-g_bm[c]);
      g_w2s[b*Cn+c]=sigmoidf(w2);
    }
  }
}

// ---------------- K10: final elementwise combine (float4) ----------------
__global__ void k10_final(const float* __restrict__ x, float* __restrict__ out){
  const int plane=blockIdx.x;
  const int bg=plane>>5;
  const float w2=g_w2s[plane];
  const float4* xp=(const float4*)(x+(size_t)plane*HWn);
  const float4* wp=(const float4*)(g_W1+(size_t)bg*HWn);
  float4* op=(float4*)(out+(size_t)plane*HWn);
  for(int i=threadIdx.x;i<HWn/4;i+=blockDim.x){
    const float4 xv=xp[i], wv=wp[i];
    float4 o;
    o.x=xv.x*(sigmoidf(wv.x)+w2);
    o.y=xv.y*(sigmoidf(wv.y)+w2);
    o.z=xv.z*(sigmoidf(wv.z)+w2);
    o.w=xv.w*(sigmoidf(wv.w)+w2);
    op[i]=o;
  }
}

// ---------------- launch ----------------
extern "C" void kernel_launch(void* const* d_in, const int* in_sizes, int n_in,
                              void* d_out, int out_size){
  const float* x  =(const float*)d_in[0];
  const float* w1 =(const float*)d_in[1];
  const float* b1 =(const float*)d_in[2];
  const float* w3a=(const float*)d_in[3];
  const float* b3a=(const float*)d_in[4];
  const float* w3b=(const float*)d_in[5];
  const float* b3b=(const float*)d_in[6];
  const float* gnw=(const float*)d_in[7];
  const float* gnb=(const float*)d_in[8];
  float* out=(float*)d_out;

  k1_plane<<<BGn*CGn,128>>>(x);
  k2_conv1<<<BGn,128>>>(w1,b1);
  k3_stats<<<BGn*CGn,128>>>(x);
  k45<<<11,288>>>(gnb,w3a,b3a,w3b);
  k5c<<<BGn,CGn>>>(w3a,b3a,gnw,gnb);
  k6_fused<<<dim3(7,Bn,Gn),448>>>(x);
  k7_softmax<<<dim3(2,Bn),256>>>();
  k8_T<<<Bn*Cn,256>>>(x);
  k9_A2<<<Bn,256>>>(w3b,b3b);
  k10_final<<<BGn*CGn,256>>>(x,out);
}